// round 2
// baseline (speedup 1.0000x reference)
#include <cuda_runtime.h>

#define SDIM 7
#define NCELL 49
#define CH 30
#define NUM_CLASSES 20
#define CONF_THR 0.25f
#define IOU_THR 0.45f
#define EPSF 1e-6f

__global__ void yolo_decode_nms_kernel(const float* __restrict__ x,
                                       float* __restrict__ out, int out_size) {
    __shared__ float dec[NCELL][6];   // decoded, cell order
    __shared__ float srt[NCELL][6];   // sorted by conf desc (stable)
    __shared__ int   keep[NCELL];

    const int t = threadIdx.x;

    // ---- Decode one cell per thread ----
    if (t < NCELL) {
        const float* c = x + t * CH;
        float p[CH];
        #pragma unroll
        for (int i = 0; i < CH; i++) {
            p[i] = 1.0f / (1.0f + expf(-c[i]));
        }

        // class argmax (first index wins ties)
        int bestc = 0;
        float bestv = p[0];
        #pragma unroll
        for (int i = 1; i < NUM_CLASSES; i++) {
            if (p[i] > bestv) { bestv = p[i]; bestc = i; }
        }

        // box select: conf0 = p[20], conf1 = p[25]; argmax -> box0 on tie
        const float conf0 = p[NUM_CLASSES + 0];
        const float conf1 = p[NUM_CLASSES + 5];
        const int  bb   = (conf1 > conf0) ? 1 : 0;
        const float pconf = bb ? conf1 : conf0;
        const int   boff  = NUM_CLASSES + 1 + 5 * bb;
        const float bx = p[boff + 0];
        const float by = p[boff + 1];
        const float bw = p[boff + 2];
        const float bh = p[boff + 3];

        const int gy = t / SDIM;       // row (h)
        const int gx = t - gy * SDIM;  // col (w)
        const float stride = 448.0f / (float)SDIM;  // 64

        dec[t][0] = (float)bestc;
        dec[t][1] = pconf;
        dec[t][2] = (bx + (float)gx) * stride;
        dec[t][3] = (by + (float)gy) * stride;
        dec[t][4] = bw * (float)SDIM * stride;
        dec[t][5] = bh * (float)SDIM * stride;
    }
    __syncthreads();

    // ---- Stable sort by conf descending (rank via counting) ----
    if (t < NCELL) {
        const float ci = dec[t][1];
        int rank = 0;
        #pragma unroll 7
        for (int j = 0; j < NCELL; j++) {
            const float cj = dec[j][1];
            // descending; ties broken by original index ascending (stable argsort of -conf)
            if (cj > ci || (cj == ci && j < t)) rank++;
        }
        #pragma unroll
        for (int k = 0; k < 6; k++) srt[rank][k] = dec[t][k];
        // note: ranks are a permutation, no conflicts
    }
    __syncthreads();

    if (t < NCELL) {
        keep[t] = (srt[t][1] > CONF_THR) ? 1 : 0;
    }
    __syncthreads();

    // ---- Sequential NMS: exact fori_loop semantics ----
    for (int i = 0; i < NCELL; i++) {
        if (t < NCELL && t > i && keep[i] && srt[t][0] == srt[i][0]) {
            // iou(b[i], b[t]) in cxcywh
            const float cx1 = srt[i][2], cy1 = srt[i][3], w1 = srt[i][4], h1 = srt[i][5];
            const float cx2 = srt[t][2], cy2 = srt[t][3], w2 = srt[t][4], h2 = srt[t][5];
            const float x1min = cx1 - 0.5f * w1, x1max = cx1 + 0.5f * w1;
            const float y1min = cy1 - 0.5f * h1, y1max = cy1 + 0.5f * h1;
            const float x2min = cx2 - 0.5f * w2, x2max = cx2 + 0.5f * w2;
            const float y2min = cy2 - 0.5f * h2, y2max = cy2 + 0.5f * h2;
            const float iw = fmaxf(fminf(x1max, x2max) - fmaxf(x1min, x2min), 0.0f);
            const float ih = fmaxf(fminf(y1max, y2max) - fmaxf(y1min, y2min), 0.0f);
            const float inter = iw * ih;
            const float a1 = fabsf((x1max - x1min) * (y1max - y1min));
            const float a2 = fabsf((x2max - x2min) * (y2max - y2min));
            const float iou = inter / (a1 + a2 - inter + EPSF);
            if (iou >= IOU_THR) keep[t] = 0;
        }
        __syncthreads();
    }

    // ---- Output: boxes * keep (294 floats), then keep mask (49 floats) ----
    if (t < NCELL) {
        const float k = (float)keep[t];
        #pragma unroll
        for (int j = 0; j < 6; j++) {
            out[t * 6 + j] = srt[t][j] * k;
        }
        const int koff = NCELL * 6 + t;
        if (koff < out_size) out[koff] = k;
    }
}

extern "C" void kernel_launch(void* const* d_in, const int* in_sizes, int n_in,
                              void* d_out, int out_size) {
    const float* x = (const float*)d_in[0];
    float* out = (float*)d_out;
    yolo_decode_nms_kernel<<<1, 64>>>(x, out, out_size);
}

// round 3
// speedup vs baseline: 1.7110x; 1.7110x over previous
#include <cuda_runtime.h>

#define SDIM 7
#define NCELL 49
#define CH 30
#define NUM_CLASSES 20
#define CONF_THR 0.25f
#define IOU_THR 0.45f
#define EPSF 1e-6f

__device__ __forceinline__ float fast_sigmoid(float v) {
    // 1/(1+exp(-v)) via MUFU ex2 + rcp; ~2ulp, far within 1e-3 tolerance
    return __frcp_rn(1.0f + __expf(-v));
}

__global__ void yolo_decode_nms_kernel(const float* __restrict__ x,
                                       float* __restrict__ out, int out_size) {
    __shared__ float dec[NCELL][6];                 // decoded, cell order
    __shared__ float srt[NCELL][6];                 // sorted by conf desc (stable)
    __shared__ float geo[NCELL][5];                 // xmin, ymin, xmax, ymax, area (sorted order)
    __shared__ unsigned long long supp[NCELL];      // suppression bitmasks
    __shared__ unsigned long long keep0_bits;

    const int t = threadIdx.x;

    if (t == 63) keep0_bits = 0ull;   // covered by the first barrier

    // ---- Decode one cell per thread (raw-logit argmax; only 5 sigmoids) ----
    if (t < NCELL) {
        const float* c = x + t * CH;
        float raw[CH];
        #pragma unroll
        for (int i = 0; i < CH; i++) raw[i] = c[i];

        // class argmax on raw logits (sigmoid is monotone; first index wins ties)
        int bestc = 0;
        float bestv = raw[0];
        #pragma unroll
        for (int i = 1; i < NUM_CLASSES; i++) {
            if (raw[i] > bestv) { bestv = raw[i]; bestc = i; }
        }

        // box select on raw conf logits (box0 wins ties, matching argmax)
        const int bb = (raw[NUM_CLASSES + 5] > raw[NUM_CLASSES + 0]) ? 1 : 0;
        const int boff = NUM_CLASSES + 5 * bb;
        const float pconf = fast_sigmoid(raw[boff]);
        const float bx = fast_sigmoid(raw[boff + 1]);
        const float by = fast_sigmoid(raw[boff + 2]);
        const float bw = fast_sigmoid(raw[boff + 3]);
        const float bh = fast_sigmoid(raw[boff + 4]);

        const int gy = t / SDIM;
        const int gx = t - gy * SDIM;
        const float stride = 448.0f / (float)SDIM;  // 64

        dec[t][0] = (float)bestc;
        dec[t][1] = pconf;
        dec[t][2] = (bx + (float)gx) * stride;
        dec[t][3] = (by + (float)gy) * stride;
        dec[t][4] = bw * (float)SDIM * stride;
        dec[t][5] = bh * (float)SDIM * stride;
    }
    __syncthreads();

    // ---- Stable rank sort by conf desc + geometry + keep0 bit ----
    if (t < NCELL) {
        const float ci = dec[t][1];
        int rank = 0;
        #pragma unroll 7
        for (int j = 0; j < NCELL; j++) {
            const float cj = dec[j][1];
            if (cj > ci || (cj == ci && j < t)) rank++;
        }
        const float cls = dec[t][0];
        const float cx = dec[t][2], cy = dec[t][3];
        const float w  = dec[t][4], h  = dec[t][5];
        srt[rank][0] = cls;  srt[rank][1] = ci;
        srt[rank][2] = cx;   srt[rank][3] = cy;
        srt[rank][4] = w;    srt[rank][5] = h;
        const float xmin = cx - 0.5f * w, xmax = cx + 0.5f * w;
        const float ymin = cy - 0.5f * h, ymax = cy + 0.5f * h;
        geo[rank][0] = xmin; geo[rank][1] = ymin;
        geo[rank][2] = xmax; geo[rank][3] = ymax;
        geo[rank][4] = fabsf((xmax - xmin) * (ymax - ymin));
        if (ci > CONF_THR) atomicOr(&keep0_bits, 1ull << rank);
    }
    __syncthreads();

    // ---- Per-box suppression bitmask (all pairs in parallel, no division) ----
    if (t < NCELL) {
        const float cls_i = srt[t][0];
        const float xmin_i = geo[t][0], ymin_i = geo[t][1];
        const float xmax_i = geo[t][2], ymax_i = geo[t][3];
        const float a_i = geo[t][4];
        unsigned long long m = 0ull;
        for (int j = t + 1; j < NCELL; j++) {
            if (srt[j][0] == cls_i) {
                const float iw = fmaxf(fminf(xmax_i, geo[j][2]) - fmaxf(xmin_i, geo[j][0]), 0.0f);
                const float ih = fmaxf(fminf(ymax_i, geo[j][3]) - fmaxf(ymin_i, geo[j][1]), 0.0f);
                const float inter = iw * ih;
                // inter/(a_i+a_j-inter+eps) >= IOU_THR  (denominator > 0 always)
                if (inter >= IOU_THR * (a_i + geo[j][4] - inter + EPSF)) m |= (1ull << j);
            }
        }
        supp[t] = m;
    }
    __syncthreads();

    // ---- Sequential keep propagation: scalar bitmask loop, run in every thread ----
    unsigned long long keepm = keep0_bits;
    #pragma unroll
    for (int i = 0; i < NCELL; i++) {
        const unsigned long long sel = 0ull - ((keepm >> i) & 1ull);
        keepm &= ~(supp[i] & sel);
    }

    // ---- Output: boxes * keep (294 floats), then keep mask (49 floats) ----
    if (t < NCELL) {
        const float k = (float)((keepm >> t) & 1ull);
        #pragma unroll
        for (int j = 0; j < 6; j++) out[t * 6 + j] = srt[t][j] * k;
        const int koff = NCELL * 6 + t;
        if (koff < out_size) out[koff] = k;
    }
}

extern "C" void kernel_launch(void* const* d_in, const int* in_sizes, int n_in,
                              void* d_out, int out_size) {
    const float* x = (const float*)d_in[0];
    float* out = (float*)d_out;
    yolo_decode_nms_kernel<<<1, 64>>>(x, out, out_size);
}

// round 4
// speedup vs baseline: 2.1219x; 1.2401x over previous
#include <cuda_runtime.h>

#define SDIM 7
#define NCELL 49
#define CH 30
#define NC 20
#define CONF_THR 0.25f
#define IOU_THR 0.45f
#define EPSF 1e-6f
#define NFLOAT (NCELL * CH)   // 1470
#define NVEC4 (NFLOAT / 4)    // 367 (tail of 2)

__device__ __forceinline__ float fsig(float v) {
    return __frcp_rn(1.0f + __expf(-v));
}

__global__ void __launch_bounds__(64, 1)
yolo_decode_nms_kernel(const float4* __restrict__ x4,
                       const float* __restrict__ x,
                       float* __restrict__ out, int out_size) {
    __shared__ float4 xs4[NVEC4 + 1];
    __shared__ float conf[NCELL];
    __shared__ float srt[NCELL][6];
    __shared__ float geo[NCELL][5];
    __shared__ unsigned long long supp[NCELL];

    float* xs = (float*)xs4;
    const int t = threadIdx.x;

    // ---- Phase 0: coalesced cooperative staging of the whole input ----
    #pragma unroll
    for (int i = t; i < NVEC4; i += 64) xs4[i] = x4[i];
    if (t < 2) xs[NVEC4 * 4 + t] = x[NVEC4 * 4 + t];
    __syncthreads();

    // ---- Phase 1: decode conf + class per cell; box vals stay in registers ----
    float bx = 0.f, by = 0.f, bw = 0.f, bh = 0.f, cls = 0.f, myconf = 0.f;
    if (t < NCELL) {
        const float* c = xs + t * CH;
        float raw[CH];
        #pragma unroll
        for (int i = 0; i < CH; i++) raw[i] = c[i];

        // tree max over 20 class logits (sigmoid monotone -> argmax on logits)
        float m01 = fmaxf(raw[0], raw[1]),  m23 = fmaxf(raw[2], raw[3]);
        float m45 = fmaxf(raw[4], raw[5]),  m67 = fmaxf(raw[6], raw[7]);
        float m89 = fmaxf(raw[8], raw[9]),  mab = fmaxf(raw[10], raw[11]);
        float mcd = fmaxf(raw[12], raw[13]), mef = fmaxf(raw[14], raw[15]);
        float mgh = fmaxf(raw[16], raw[17]), mij = fmaxf(raw[18], raw[19]);
        float q0 = fmaxf(m01, m23), q1 = fmaxf(m45, m67), q2 = fmaxf(m89, mab);
        float q3 = fmaxf(mcd, mef), q4 = fmaxf(mgh, mij);
        float mv = fmaxf(fmaxf(fmaxf(q0, q1), fmaxf(q2, q3)), q4);
        unsigned em = 0;
        #pragma unroll
        for (int i = 0; i < NC; i++) em |= (raw[i] == mv) ? (1u << i) : 0u;
        cls = (float)(__ffs(em) - 1);   // first index wins ties

        // box select on raw conf logits (box0 wins ties)
        const float c0 = raw[NC + 0], c1 = raw[NC + 5];
        const int bb = (c1 > c0) ? 1 : 0;
        const int boff = NC + 5 * bb;
        myconf = fsig(fmaxf(c0, c1));
        bx = fsig(raw[boff + 1]);
        by = fsig(raw[boff + 2]);
        bw = fsig(raw[boff + 3]);
        bh = fsig(raw[boff + 4]);
        conf[t] = myconf;
    }
    __syncthreads();

    // ---- Phase 2: stable rank (conf desc), scatter decoded box to sorted slot ----
    if (t < NCELL) {
        int rank = 0;
        #pragma unroll
        for (int j = 0; j < NCELL; j++) {
            const float cj = conf[j];
            if (cj > myconf || (cj == myconf && j < t)) rank++;
        }
        const int gy = t / SDIM;
        const int gx = t - gy * SDIM;
        const float stride = 448.0f / (float)SDIM;  // 64
        const float cx = (bx + (float)gx) * stride;
        const float cy = (by + (float)gy) * stride;
        const float w  = bw * (float)SDIM * stride;
        const float h  = bh * (float)SDIM * stride;
        srt[rank][0] = cls;  srt[rank][1] = myconf;
        srt[rank][2] = cx;   srt[rank][3] = cy;
        srt[rank][4] = w;    srt[rank][5] = h;
        const float xmin = cx - 0.5f * w, xmax = cx + 0.5f * w;
        const float ymin = cy - 0.5f * h, ymax = cy + 0.5f * h;
        geo[rank][0] = xmin; geo[rank][1] = ymin;
        geo[rank][2] = xmax; geo[rank][3] = ymax;
        geo[rank][4] = fabsf((xmax - xmin) * (ymax - ymin));
    }
    __syncthreads();

    // ---- Phase 3: suppression bitmask, branchless, fully unrolled ----
    if (t < NCELL) {
        const float cls_i = srt[t][0];
        const float xmin_i = geo[t][0], ymin_i = geo[t][1];
        const float xmax_i = geo[t][2], ymax_i = geo[t][3];
        const float a_i = geo[t][4];
        unsigned long long m = 0ull;
        #pragma unroll
        for (int j = 0; j < NCELL; j++) {
            const float iw = fmaxf(fminf(xmax_i, geo[j][2]) - fmaxf(xmin_i, geo[j][0]), 0.0f);
            const float ih = fmaxf(fminf(ymax_i, geo[j][3]) - fmaxf(ymin_i, geo[j][1]), 0.0f);
            const float inter = iw * ih;
            const bool hit = (j > t) & (srt[j][0] == cls_i) &
                             (inter >= IOU_THR * (a_i + geo[j][4] - inter + EPSF));
            m |= hit ? (1ull << j) : 0ull;
        }
        supp[t] = m;
    }
    __syncthreads();

    // ---- Phase 4: keep0 bits + sequential keep propagation (scalar, per-thread) ----
    unsigned long long keepm = 0ull;
    #pragma unroll
    for (int i = 0; i < NCELL; i++)
        keepm |= (srt[i][1] > CONF_THR) ? (1ull << i) : 0ull;
    #pragma unroll
    for (int i = 0; i < NCELL; i++) {
        const unsigned long long sel = 0ull - ((keepm >> i) & 1ull);
        keepm &= ~(supp[i] & sel);
    }

    // ---- Output: boxes * keep (294 floats), then keep mask (49 floats) ----
    if (t < NCELL) {
        const float k = (float)((keepm >> t) & 1ull);
        #pragma unroll
        for (int j = 0; j < 6; j++) out[t * 6 + j] = srt[t][j] * k;
        const int koff = NCELL * 6 + t;
        if (koff < out_size) out[koff] = k;
    }
}

extern "C" void kernel_launch(void* const* d_in, const int* in_sizes, int n_in,
                              void* d_out, int out_size) {
    const float* x = (const float*)d_in[0];
    float* out = (float*)d_out;
    yolo_decode_nms_kernel<<<1, 64>>>((const float4*)x, x, out, out_size);
}

// round 5
// speedup vs baseline: 2.4463x; 1.1529x over previous
#include <cuda_runtime.h>

#define SDIM 7
#define NCELL 49
#define CH 30
#define NC 20
#define CONF_THR 0.25f
#define IOU_THR 0.45f
#define EPSF 1e-6f
#define NFLOAT (NCELL * CH)   // 1470
#define NVEC4 (NFLOAT / 4)    // 367 (tail of 2)

__device__ __forceinline__ float fsig(float v) {
    return __frcp_rn(1.0f + __expf(-v));
}

__global__ void __launch_bounds__(64, 1)
yolo_decode_nms_kernel(const float4* __restrict__ x4,
                       const float* __restrict__ x,
                       float* __restrict__ out, int out_size) {
    __shared__ float4 xs4[NVEC4 + 1];
    __shared__ float conf[NCELL];
    __shared__ float srt[NCELL][6];               // sorted: cls, conf, cx, cy, w, h
    __shared__ float4 geo4[NCELL];                // xmin, ymin, xmax, ymax (sorted)
    __shared__ float area[NCELL];
    __shared__ int clsi[52];                      // padded to int4 multiple
    __shared__ unsigned char kb[64];              // conf>thr per rank
    __shared__ unsigned long long suppm[NCELL];
    __shared__ unsigned int bal[4];               // keep_lo, keep_hi, nz_lo, nz_hi

    float* xs = (float*)xs4;
    const int t = threadIdx.x;

    // ---- Phase 0: coalesced staging + padding init ----
    #pragma unroll
    for (int i = t; i < NVEC4; i += 64) xs4[i] = x4[i];
    if (t < 2) xs[NVEC4 * 4 + t] = x[NVEC4 * 4 + t];
    if (t < 3) clsi[NCELL + t] = -1;
    if (t >= NCELL) kb[t] = 0;
    __syncthreads();

    // ---- Phase 1: decode (float2 loads, tree argmax on raw logits) ----
    float bx = 0.f, by = 0.f, bw = 0.f, bh = 0.f, myconf = 0.f;
    int myclsi = 0;
    if (t < NCELL) {
        const float2* c = (const float2*)(xs + t * CH);  // t*120B, 8B-aligned
        float r[CH];
        #pragma unroll
        for (int k = 0; k < CH / 2; k++) {
            const float2 v = c[k];
            r[2 * k] = v.x; r[2 * k + 1] = v.y;
        }

        float m01 = fmaxf(r[0], r[1]),   m23 = fmaxf(r[2], r[3]);
        float m45 = fmaxf(r[4], r[5]),   m67 = fmaxf(r[6], r[7]);
        float m89 = fmaxf(r[8], r[9]),   mab = fmaxf(r[10], r[11]);
        float mcd = fmaxf(r[12], r[13]), mef = fmaxf(r[14], r[15]);
        float mgh = fmaxf(r[16], r[17]), mij = fmaxf(r[18], r[19]);
        float q0 = fmaxf(m01, m23), q1 = fmaxf(m45, m67), q2 = fmaxf(m89, mab);
        float q3 = fmaxf(mcd, mef), q4 = fmaxf(mgh, mij);
        float mv = fmaxf(fmaxf(fmaxf(q0, q1), fmaxf(q2, q3)), q4);
        unsigned em = 0;
        #pragma unroll
        for (int i = 0; i < NC; i++) em |= (r[i] == mv) ? (1u << i) : 0u;
        myclsi = __ffs(em) - 1;       // first index wins ties

        const float c0 = r[NC + 0], c1 = r[NC + 5];
        const int bb = (c1 > c0) ? 1 : 0;
        const int boff = NC + 5 * bb;
        myconf = fsig(fmaxf(c0, c1));
        bx = fsig(r[boff + 1]);
        by = fsig(r[boff + 2]);
        bw = fsig(r[boff + 3]);
        bh = fsig(r[boff + 4]);
        conf[t] = myconf;
    }
    __syncthreads();

    // ---- Phase 2: stable rank (conf desc) + scatter to sorted slots ----
    if (t < NCELL) {
        int rank = 0;
        #pragma unroll
        for (int j = 0; j < NCELL; j++) {
            const float cj = conf[j];
            if (cj > myconf || (cj == myconf && j < t)) rank++;
        }
        const int gy = t / SDIM;
        const int gx = t - gy * SDIM;
        const float stride = 448.0f / (float)SDIM;  // 64
        const float cx = (bx + (float)gx) * stride;
        const float cy = (by + (float)gy) * stride;
        const float w  = bw * (float)SDIM * stride;
        const float h  = bh * (float)SDIM * stride;
        srt[rank][0] = (float)myclsi;  srt[rank][1] = myconf;
        srt[rank][2] = cx;             srt[rank][3] = cy;
        srt[rank][4] = w;              srt[rank][5] = h;
        const float xmin = cx - 0.5f * w, xmax = cx + 0.5f * w;
        const float ymin = cy - 0.5f * h, ymax = cy + 0.5f * h;
        geo4[rank] = make_float4(xmin, ymin, xmax, ymax);
        area[rank] = fabsf((xmax - xmin) * (ymax - ymin));
        clsi[rank] = myclsi;
        kb[rank] = (myconf > CONF_THR) ? 1 : 0;
    }
    __syncthreads();

    // ---- Phase 3: sparse suppression masks (class prefilter + rare IoU) ----
    const unsigned keepbal = __ballot_sync(0xffffffffu, (t < NCELL) && kb[t]);
    unsigned long long m = 0ull;
    if (t < NCELL) {
        const int ci = clsi[t];
        unsigned long long cm = 0ull;
        const int4* cp = (const int4*)clsi;
        #pragma unroll
        for (int q = 0; q < 13; q++) {
            const int4 w4 = cp[q];
            cm |= (unsigned long long)(w4.x == ci) << (4 * q + 0);
            cm |= (unsigned long long)(w4.y == ci) << (4 * q + 1);
            cm |= (unsigned long long)(w4.z == ci) << (4 * q + 2);
            cm |= (unsigned long long)(w4.w == ci) << (4 * q + 3);
        }
        cm &= ~((2ull << t) - 1ull);   // j > t only
        const float4 g = geo4[t];
        const float a_i = area[t];
        while (cm) {
            const int j = __ffsll((long long)cm) - 1;
            cm &= cm - 1ull;
            const float4 gj = geo4[j];
            const float iw = fmaxf(fminf(g.z, gj.z) - fmaxf(g.x, gj.x), 0.0f);
            const float ih = fmaxf(fminf(g.w, gj.w) - fmaxf(g.y, gj.y), 0.0f);
            const float inter = iw * ih;
            if (inter >= IOU_THR * (a_i + area[j] - inter + EPSF)) m |= (1ull << j);
        }
        suppm[t] = m;
    }
    const unsigned nzbal = __ballot_sync(0xffffffffu, (t < NCELL) && (m != 0ull));
    if ((t & 31) == 0) { bal[t >> 5] = keepbal; bal[2 + (t >> 5)] = nzbal; }
    __syncthreads();

    // ---- Phase 4: sparse sequential keep propagation ----
    unsigned long long keepm = (unsigned long long)bal[0] |
                               ((unsigned long long)bal[1] << 32);
    unsigned long long nz = (unsigned long long)bal[2] |
                            ((unsigned long long)bal[3] << 32);
    while (nz) {                         // ascending i order via ffs
        const int i = __ffsll((long long)nz) - 1;
        nz &= nz - 1ull;
        if ((keepm >> i) & 1ull) keepm &= ~suppm[i];
    }

    // ---- Output: coalesced; boxes*keep [0,294), keep mask [294,343) ----
    const int total = NCELL * 6 + NCELL;  // 343
    for (int p = t; p < total && p < out_size; p += 64) {
        float v;
        if (p < NCELL * 6) {
            const int row = p / 6;
            const int col = p - row * 6;
            v = srt[row][col] * (float)((keepm >> row) & 1ull);
        } else {
            const int row = p - NCELL * 6;
            v = (float)((keepm >> row) & 1ull);
        }
        out[p] = v;
    }
}

extern "C" void kernel_launch(void* const* d_in, const int* in_sizes, int n_in,
                              void* d_out, int out_size) {
    const float* x = (const float*)d_in[0];
    float* out = (float*)d_out;
    yolo_decode_nms_kernel<<<1, 64>>>((const float4*)x, x, out, out_size);
}